// round 9
// baseline (speedup 1.0000x reference)
#include <cuda_runtime.h>
#include <cuda_bf16.h>
#include <cuda_fp16.h>
#include <math.h>
#include <stdint.h>

// Problem constants
#define BB 4
#define LL 2048
#define DD 1024
#define HH 16
#define KVH 4
#define HD 64
#define ML (BB*LL)          // 8192 rows

// Scratch buffers (device globals; no allocation allowed)
__device__ float g_q[ML * HH * HD];     // 8192 x 1024
__device__ float g_k[ML * KVH * HD];    // 8192 x 256
__device__ float g_v[ML * KVH * HD];    // 8192 x 256
__device__ float g_attn[ML * HH * HD];  // 8192 x 1024

// ---------------------------------------------------------------------------
// mma / ldmatrix helpers
// ---------------------------------------------------------------------------
__device__ __forceinline__ void mma_f16(float c[4], const uint32_t a[4],
                                        uint32_t b0, uint32_t b1) {
    asm volatile(
        "mma.sync.aligned.m16n8k16.row.col.f32.f16.f16.f32 "
        "{%0,%1,%2,%3}, {%4,%5,%6,%7}, {%8,%9}, {%0,%1,%2,%3};"
        : "+f"(c[0]), "+f"(c[1]), "+f"(c[2]), "+f"(c[3])
        : "r"(a[0]), "r"(a[1]), "r"(a[2]), "r"(a[3]), "r"(b0), "r"(b1));
}

__device__ __forceinline__ uint32_t packh2(float lo, float hi) {
    __half2 h = __floats2half2_rn(lo, hi);
    return *(uint32_t*)&h;
}

__device__ __forceinline__ void ldsm_x4(uint32_t& r0, uint32_t& r1,
                                        uint32_t& r2, uint32_t& r3,
                                        uint32_t addr) {
    asm volatile("ldmatrix.sync.aligned.m8n8.x4.shared.b16 {%0,%1,%2,%3}, [%4];"
                 : "=r"(r0), "=r"(r1), "=r"(r2), "=r"(r3) : "r"(addr));
}
__device__ __forceinline__ void ldsm_x4_t(uint32_t& r0, uint32_t& r1,
                                          uint32_t& r2, uint32_t& r3,
                                          uint32_t addr) {
    asm volatile("ldmatrix.sync.aligned.m8n8.x4.trans.shared.b16 {%0,%1,%2,%3}, [%4];"
                 : "=r"(r0), "=r"(r1), "=r"(r2), "=r"(r3) : "r"(addr));
}

// ---------------------------------------------------------------------------
// F16 tensor-core GEMM (unchanged from R8): C[M,N] = A[M,K] @ B[K,N].
// ---------------------------------------------------------------------------
#define GBM 128
#define GBN 128
#define GBK 32

__global__ __launch_bounds__(256, 1) void gemm_f16(const float* __restrict__ A,
                                                   const float* __restrict__ B,
                                                   float* __restrict__ C,
                                                   int M, int N, int K,
                                                   int do_rope,
                                                   const float* __restrict__ cosf_,
                                                   const float* __restrict__ sinf_) {
    __shared__ uint32_t As2[GBM][20];
    __shared__ uint32_t Bs2[GBK / 2][136];

    const int tid  = threadIdx.x;
    const int bm   = blockIdx.y * GBM;
    const int bn   = blockIdx.x * GBN;
    const int lane = tid & 31;
    const int warp = tid >> 5;
    const int g    = lane >> 2;
    const int tig  = lane & 3;
    const int wm   = (warp & 3) * 32;
    const int wn   = (warp >> 2) * 64;

    const int a_k4 = tid & 7;
    const int a_m  = tid >> 3;
    const int b_k2 = tid >> 4;
    const int b_n8 = (tid & 15) * 8;

    float c[2][8][4];
#pragma unroll
    for (int mt = 0; mt < 2; ++mt)
#pragma unroll
        for (int nt = 0; nt < 8; ++nt)
#pragma unroll
            for (int i = 0; i < 4; ++i) c[mt][nt][i] = 0.f;

    const float* Abase = A + (size_t)(bm + a_m) * K + 4 * a_k4;
    const float* B0    = B + (size_t)(2 * b_k2) * N + bn + b_n8;
    const float* B1    = B0 + N;

    float4 Ar[4], Br0[2], Br1[2];
#pragma unroll
    for (int i = 0; i < 4; ++i) Ar[i] = *(const float4*)(Abase + (size_t)(32 * i) * K);
    Br0[0] = *(const float4*)(B0);     Br0[1] = *(const float4*)(B0 + 4);
    Br1[0] = *(const float4*)(B1);     Br1[1] = *(const float4*)(B1 + 4);

    const int ktiles = K / GBK;
    for (int kt = 0; kt < ktiles; ++kt) {
#pragma unroll
        for (int i = 0; i < 4; ++i) {
            As2[a_m + 32 * i][2 * a_k4 + 0] = packh2(Ar[i].x, Ar[i].y);
            As2[a_m + 32 * i][2 * a_k4 + 1] = packh2(Ar[i].z, Ar[i].w);
        }
        {
            uint4 w0, w1;
            w0.x = packh2(Br0[0].x, Br1[0].x);
            w0.y = packh2(Br0[0].y, Br1[0].y);
            w0.z = packh2(Br0[0].z, Br1[0].z);
            w0.w = packh2(Br0[0].w, Br1[0].w);
            w1.x = packh2(Br0[1].x, Br1[1].x);
            w1.y = packh2(Br0[1].y, Br1[1].y);
            w1.z = packh2(Br0[1].z, Br1[1].z);
            w1.w = packh2(Br0[1].w, Br1[1].w);
            *(uint4*)&Bs2[b_k2][b_n8]     = w0;
            *(uint4*)&Bs2[b_k2][b_n8 + 4] = w1;
        }
        __syncthreads();

        if (kt + 1 < ktiles) {
            const float* ap = Abase + (kt + 1) * GBK;
            const float* bp0 = B0 + (size_t)(kt + 1) * GBK * N;
            const float* bp1 = bp0 + N;
#pragma unroll
            for (int i = 0; i < 4; ++i) Ar[i] = *(const float4*)(ap + (size_t)(32 * i) * K);
            Br0[0] = *(const float4*)(bp0);  Br0[1] = *(const float4*)(bp0 + 4);
            Br1[0] = *(const float4*)(bp1);  Br1[1] = *(const float4*)(bp1 + 4);
        }

#pragma unroll
        for (int ks = 0; ks < 2; ++ks) {
            const int k2b = 8 * ks;
            uint32_t afr[2][4];
#pragma unroll
            for (int mt = 0; mt < 2; ++mt) {
                const int m0 = wm + 16 * mt;
                afr[mt][0] = As2[m0 + g    ][k2b + tig    ];
                afr[mt][1] = As2[m0 + g + 8][k2b + tig    ];
                afr[mt][2] = As2[m0 + g    ][k2b + tig + 4];
                afr[mt][3] = As2[m0 + g + 8][k2b + tig + 4];
            }
#pragma unroll
            for (int nt = 0; nt < 8; ++nt) {
                const int n0 = wn + 8 * nt;
                const uint32_t b0 = Bs2[k2b + tig    ][n0 + g];
                const uint32_t b1 = Bs2[k2b + tig + 4][n0 + g];
                mma_f16(c[0][nt], afr[0], b0, b1);
                mma_f16(c[1][nt], afr[1], b0, b1);
            }
        }
        __syncthreads();
    }

#pragma unroll
    for (int mt = 0; mt < 2; ++mt) {
        const int row0 = bm + wm + 16 * mt + g;
#pragma unroll
        for (int nt = 0; nt < 8; ++nt) {
            const int col = bn + wn + 8 * nt + 2 * tig;
            float2 lo; lo.x = c[mt][nt][0]; lo.y = c[mt][nt][1];
            float2 hi; hi.x = c[mt][nt][2]; hi.y = c[mt][nt][3];
            if (do_rope) {
                const int i  = (col & (HD - 1)) >> 1;
                const int l0 = row0 & (LL - 1);
                const int l1 = (row0 + 8) & (LL - 1);
                float c0 = cosf_[l0 * 32 + i], s0 = sinf_[l0 * 32 + i];
                float c1 = cosf_[l1 * 32 + i], s1 = sinf_[l1 * 32 + i];
                float2 r0, r1;
                r0.x = lo.x * c0 - lo.y * s0;  r0.y = lo.x * s0 + lo.y * c0;
                r1.x = hi.x * c1 - hi.y * s1;  r1.y = hi.x * s1 + hi.y * c1;
                lo = r0; hi = r1;
            }
            *(float2*)(C + (size_t)row0 * N + col)       = lo;
            *(float2*)(C + (size_t)(row0 + 8) * N + col) = hi;
        }
    }
}

// ---------------------------------------------------------------------------
// F16 flash attention with ldmatrix fragment loads (causal, GQA).
// 256 threads = 8 warps x 16 query rows; KV tiles of 64 keys.
// SMEM: plain row-major f16, stride 72 halfs (144B) -> all ldmatrix rows
// land on distinct 16B segments (16j mod 128 distinct), conflict-free.
// Overlay: Qs[128][72] == Ks[64][72] + Vs[64][72] (18432 B).
// Fragment semantics identical to R8 (rel_err must match 5.24e-4).
// ---------------------------------------------------------------------------
__global__ __launch_bounds__(256) void attn_mma(const float* __restrict__ qg,
                                                const float* __restrict__ kg,
                                                const float* __restrict__ vg,
                                                float* __restrict__ og) {
    __shared__ __align__(16) __half smh[128 * 72];
    uint32_t* smw = (uint32_t*)smh;                       // word view (half2)
    const uint32_t smem_base = (uint32_t)__cvta_generic_to_shared(smh);
    const uint32_t Ks_base = smem_base;
    const uint32_t Vs_base = smem_base + 64 * 72 * 2;

    const int tid  = threadIdx.x;
    const int lane = tid & 31;
    const int warp = tid >> 5;
    const int g    = lane >> 2;
    const int tig  = lane & 3;
    const int j8   = lane & 7;
    const int grp  = lane >> 3;
    const int qblk = blockIdx.x;
    const int h    = blockIdx.y;
    const int b    = blockIdx.z;
    const int kvh  = h >> 2;
    const int qb0  = qblk * 128;
    const int wl   = warp * 16;

    // per-lane ldmatrix row/col offsets
    const int kr = 8 * (grp >> 1) + j8;   // K (non-trans): n-sub select
    const int kc = 8 * (grp & 1);         //               k-half select
    const int vr = 8 * (grp & 1) + j8;    // V (trans) / Q: row-half select
    const int vc = 8 * (grp >> 1);        //               col-half select

    const float qscale = 0.125f * 1.4426950408889634f;   // (1/sqrt(64))*log2(e)

    // ---- Phase 0: stage Q (scaled f16, row-major stride 72)
    {
        const int row = tid >> 1, hf = tid & 1;
        const float4* src = (const float4*)(qg + (((size_t)b * LL + qb0 + row) * HH + h) * HD + 32 * hf);
        uint32_t* dst = smw + row * 36 + 16 * hf;
#pragma unroll
        for (int u = 0; u < 8; ++u) {
            float4 tv = src[u];
            dst[2 * u + 0] = packh2(tv.x * qscale, tv.y * qscale);
            dst[2 * u + 1] = packh2(tv.z * qscale, tv.w * qscale);
        }
    }
    __syncthreads();

    uint32_t qf[4][4];
#pragma unroll
    for (int ks = 0; ks < 4; ++ks) {
        uint32_t addr = smem_base + (uint32_t)(((wl + vr) * 72 + 16 * ks + vc) * 2);
        ldsm_x4(qf[ks][0], qf[ks][1], qf[ks][2], qf[ks][3], addr);
    }
    __syncthreads();   // Qs dead; Ks/Vs may overwrite

    float oacc[8][4];
#pragma unroll
    for (int nt = 0; nt < 8; ++nt)
#pragma unroll
        for (int i = 0; i < 4; ++i) oacc[nt][i] = 0.f;
    float mrow0 = -INFINITY, mrow1 = -INFINITY;
    float lrow0 = 0.f, lrow1 = 0.f;

    const int ntiles = 2 * (qblk + 1);

    for (int t = 0; t < ntiles; ++t) {
        const int j0 = t * 64;

        // ---- stage K and V tiles, row-major f16 (stride 72)
        {
            const int jj = tid & 63, seg = tid >> 6;      // 16 d-values per thread
            const float4* kp = (const float4*)(kg + (((size_t)b * LL + j0 + jj) * KVH + kvh) * HD + 16 * seg);
            const float4* vp = (const float4*)(vg + (((size_t)b * LL + j0 + jj) * KVH + kvh) * HD + 16 * seg);
            uint32_t* kd = smw + jj * 36 + 8 * seg;
            uint32_t* vd = smw + 64 * 36 + jj * 36 + 8 * seg;
#pragma unroll
            for (int u = 0; u < 4; ++u) {
                float4 tv = kp[u];
                kd[2 * u + 0] = packh2(tv.x, tv.y);
                kd[2 * u + 1] = packh2(tv.z, tv.w);
            }
#pragma unroll
            for (int u = 0; u < 4; ++u) {
                float4 tv = vp[u];
                vd[2 * u + 0] = packh2(tv.x, tv.y);
                vd[2 * u + 1] = packh2(tv.z, tv.w);
            }
        }
        __syncthreads();

        if (j0 <= qb0 + wl + 15) {     // warp has visible rows in this tile
            // ---- S = Q @ K^T (f16, ldmatrix B-frags: 2 n-tiles per x4)
            float sc[8][4];
#pragma unroll
            for (int nt = 0; nt < 8; ++nt)
#pragma unroll
                for (int i = 0; i < 4; ++i) sc[nt][i] = 0.f;

#pragma unroll
            for (int ks = 0; ks < 4; ++ks)
#pragma unroll
                for (int ntp = 0; ntp < 4; ++ntp) {
                    uint32_t b0, b1, b2, b3;
                    uint32_t addr = Ks_base + (uint32_t)(((16 * ntp + kr) * 72 + 16 * ks + kc) * 2);
                    ldsm_x4(b0, b1, b2, b3, addr);
                    mma_f16(sc[2 * ntp    ], qf[ks], b0, b1);
                    mma_f16(sc[2 * ntp + 1], qf[ks], b2, b3);
                }

            // ---- causal mask (diagonal tile only)
            if (j0 + 63 > qb0 + wl) {
                const int r0 = qb0 + wl + g;
#pragma unroll
                for (int nt = 0; nt < 8; ++nt) {
                    const int c0 = j0 + 8 * nt + 2 * tig;
                    if (c0     > r0    ) sc[nt][0] = -INFINITY;
                    if (c0 + 1 > r0    ) sc[nt][1] = -INFINITY;
                    if (c0     > r0 + 8) sc[nt][2] = -INFINITY;
                    if (c0 + 1 > r0 + 8) sc[nt][3] = -INFINITY;
                }
            }

            // ---- online softmax (base-2)
            float mx0 = -INFINITY, mx1 = -INFINITY;
#pragma unroll
            for (int nt = 0; nt < 8; ++nt) {
                mx0 = fmaxf(mx0, fmaxf(sc[nt][0], sc[nt][1]));
                mx1 = fmaxf(mx1, fmaxf(sc[nt][2], sc[nt][3]));
            }
            mx0 = fmaxf(mx0, __shfl_xor_sync(0xffffffffu, mx0, 1));
            mx0 = fmaxf(mx0, __shfl_xor_sync(0xffffffffu, mx0, 2));
            mx1 = fmaxf(mx1, __shfl_xor_sync(0xffffffffu, mx1, 1));
            mx1 = fmaxf(mx1, __shfl_xor_sync(0xffffffffu, mx1, 2));

            const float mnew0 = fmaxf(mrow0, mx0);
            const float mnew1 = fmaxf(mrow1, mx1);
            const float corr0 = exp2f(mrow0 - mnew0);
            const float corr1 = exp2f(mrow1 - mnew1);
            mrow0 = mnew0; mrow1 = mnew1;
            lrow0 *= corr0; lrow1 *= corr1;

            float sum0 = 0.f, sum1 = 0.f;
#pragma unroll
            for (int nt = 0; nt < 8; ++nt) {
                oacc[nt][0] *= corr0; oacc[nt][1] *= corr0;
                oacc[nt][2] *= corr1; oacc[nt][3] *= corr1;
                sc[nt][0] = exp2f(sc[nt][0] - mnew0); sum0 += sc[nt][0];
                sc[nt][1] = exp2f(sc[nt][1] - mnew0); sum0 += sc[nt][1];
                sc[nt][2] = exp2f(sc[nt][2] - mnew1); sum1 += sc[nt][2];
                sc[nt][3] = exp2f(sc[nt][3] - mnew1); sum1 += sc[nt][3];
            }
            lrow0 += sum0; lrow1 += sum1;

            // ---- O += P @ V (f16; ldmatrix.trans B-frags, P packed in regs)
#pragma unroll
            for (int ksp = 0; ksp < 4; ++ksp) {
                uint32_t pa[4];
                pa[0] = packh2(sc[2 * ksp    ][0], sc[2 * ksp    ][1]);
                pa[1] = packh2(sc[2 * ksp    ][2], sc[2 * ksp    ][3]);
                pa[2] = packh2(sc[2 * ksp + 1][0], sc[2 * ksp + 1][1]);
                pa[3] = packh2(sc[2 * ksp + 1][2], sc[2 * ksp + 1][3]);
#pragma unroll
                for (int ntp = 0; ntp < 4; ++ntp) {
                    uint32_t b0, b1, b2, b3;
                    uint32_t addr = Vs_base + (uint32_t)(((16 * ksp + vr) * 72 + 16 * ntp + vc) * 2);
                    ldsm_x4_t(b0, b1, b2, b3, addr);
                    mma_f16(oacc[2 * ntp    ], pa, b0, b1);
                    mma_f16(oacc[2 * ntp + 1], pa, b2, b3);
                }
            }
        }
        __syncthreads();   // protect Ks/Vs before next tile's load
    }

    // ---- finalize
    lrow0 += __shfl_xor_sync(0xffffffffu, lrow0, 1);
    lrow0 += __shfl_xor_sync(0xffffffffu, lrow0, 2);
    lrow1 += __shfl_xor_sync(0xffffffffu, lrow1, 1);
    lrow1 += __shfl_xor_sync(0xffffffffu, lrow1, 2);
    const float inv0 = 1.f / lrow0;
    const float inv1 = 1.f / lrow1;
    const int r0 = qb0 + wl + g;
#pragma unroll
    for (int nt = 0; nt < 8; ++nt) {
        const int col = 8 * nt + 2 * tig;
        float2 w0; w0.x = oacc[nt][0] * inv0; w0.y = oacc[nt][1] * inv0;
        float2 w1; w1.x = oacc[nt][2] * inv1; w1.y = oacc[nt][3] * inv1;
        *(float2*)(og + (((size_t)b * LL + r0    ) * HH + h) * HD + col) = w0;
        *(float2*)(og + (((size_t)b * LL + r0 + 8) * HH + h) * HD + col) = w1;
    }
}

// ---------------------------------------------------------------------------
// Launch
// ---------------------------------------------------------------------------
extern "C" void kernel_launch(void* const* d_in, const int* in_sizes, int n_in,
                              void* d_out, int out_size) {
    const float* x        = (const float*)d_in[0];
    const float* wq       = (const float*)d_in[1];
    const float* wk       = (const float*)d_in[2];
    const float* wv       = (const float*)d_in[3];
    const float* wo       = (const float*)d_in[4];
    const float* freqs_c  = (const float*)d_in[5];
    const float* freqs_s  = (const float*)d_in[6];
    // d_in[7] = mask: all-true by construction; causal mask handled in-kernel.
    float* out = (float*)d_out;

    float *qb, *kb, *vb, *ab;
    cudaGetSymbolAddress((void**)&qb, g_q);
    cudaGetSymbolAddress((void**)&kb, g_k);
    cudaGetSymbolAddress((void**)&vb, g_v);
    cudaGetSymbolAddress((void**)&ab, g_attn);

    // QKV projections (f16 tensor cores; RoPE fused into Q/K epilogues)
    {
        dim3 gq(HH * HD / GBN, ML / GBM);     // (8, 64)
        gemm_f16<<<gq, 256>>>(x, wq, qb, ML, HH * HD, DD, 1, freqs_c, freqs_s);
        dim3 gk(KVH * HD / GBN, ML / GBM);    // (2, 64)
        gemm_f16<<<gk, 256>>>(x, wk, kb, ML, KVH * HD, DD, 1, freqs_c, freqs_s);
        gemm_f16<<<gk, 256>>>(x, wv, vb, ML, KVH * HD, DD, 0, nullptr, nullptr);
    }

    // Attention (f16 tensor cores + ldmatrix)
    {
        dim3 ga(LL / 128, HH, BB);            // (16, 16, 4)
        attn_mma<<<ga, 256>>>(qb, kb, vb, ab);
    }

    // Output projection (f16 tensor cores)
    {
        dim3 go(DD / GBN, ML / GBM);          // (8, 64)
        gemm_f16<<<go, 256>>>(ab, wo, out, ML, DD, DD, 0, nullptr, nullptr);
    }
}